// round 5
// baseline (speedup 1.0000x reference)
#include <cuda_runtime.h>
#include <cuda_bf16.h>
#include <cstdint>
#include <cstddef>

// Problem constants (fixed by the reference).
#define NN   8192   // N_NODES (rows/cols of adj, K of the big GEMM)
#define INF  256    // IN_FEATURES
#define OUTF 32     // OUT_FEATURES

// ---------------------------------------------------------------------------
// Scratch: HW = h @ W, split into bf16 hi/lo, stored TRANSPOSED as [dtype][n][k]
// so that rows are n (OUTF of them) and k is contiguous — this is exactly the
// layout ldmatrix (non-trans) needs to produce the mma.sync B fragment.
// Size: 2 * 32 * 8192 * 2B = 1 MB. Static __device__ global (allowed).
// ---------------------------------------------------------------------------
__device__ __nv_bfloat16 g_B[2 * OUTF * NN];

// ---------------------------------------------------------------------------
// Kernel 1: HW = h @ W  (fp32), then hi/lo bf16 split into g_B (transposed).
// Grid: 1024 blocks x 256 threads; block handles 8 rows x all 32 cols.
// ---------------------------------------------------------------------------
__global__ void __launch_bounds__(256) hw_kernel(const float* __restrict__ h,
                                                 const float* __restrict__ W) {
    __shared__ float Ws[INF * OUTF];            // 32 KB, [k][n] row-major
    const int t = threadIdx.x;
    for (int i = t; i < INF * OUTF; i += 256) Ws[i] = W[i];
    __syncthreads();

    const int c   = t & 31;                     // output column n
    const int r   = t >> 5;                     // row within block (0..7)
    const int row = blockIdx.x * 8 + r;         // global k-row of HW

    const float4* hrow = reinterpret_cast<const float4*>(h + (size_t)row * INF);
    float acc = 0.f;
#pragma unroll 8
    for (int k4 = 0; k4 < INF / 4; ++k4) {
        const float4 hv = hrow[k4];             // broadcast across the warp
        const float* wp = &Ws[(k4 * 4) * OUTF + c];
        acc += hv.x * wp[0];
        acc += hv.y * wp[OUTF];
        acc += hv.z * wp[2 * OUTF];
        acc += hv.w * wp[3 * OUTF];
    }

    const __nv_bfloat16 hi = __float2bfloat16_rn(acc);
    const float rem        = acc - __bfloat162float(hi);
    const __nv_bfloat16 lo = __float2bfloat16_rn(rem);

    g_B[c * NN + row]             = hi;         // plane 0: hi
    g_B[OUTF * NN + c * NN + row] = lo;         // plane 1: lo
}

// ---------------------------------------------------------------------------
// Kernel 2: out[8192,32] = adj[8192,8192] @ HW  via bf16 mma.sync (hi+lo).
//
// CTA: BM=64 rows, all N=32, K streamed in BK=64 chunks (128 chunks).
// 256 threads = 8 warps laid out 4(m) x 2(n); each warp: m16 x n16
// (= 2 mma n-tiles), fp32 accumulators in registers.
//
// Per chunk:
//   A: LDG float4 fp32 (chunk c+1) -> regs while MMA(c) runs; cvt -> STS bf16.
//   B: cp.async bf16 hi/lo chunk from g_B (L2-resident) into smem.
// smem rows are padded to 144 B (72 halfs): row stride = 36 words = 4 (mod 32)
// -> bank-conflict-free for ldmatrix (8 rows x 16B per 8x8 matrix).
//
// 2-stage double buffer, static 36 KB smem (no FuncSetAttribute needed).
// ---------------------------------------------------------------------------
#define BK      64
#define PITCHB  144                  // bytes per smem row (64 halfs + 8 pad)
#define A_BYTES (64 * PITCHB)        // 9216: A region = 64 rows (m)
#define STAGEB  (2 * 64 * PITCHB)    // 18432: A (64 rows) + B (64 rows = 2x32 n)
#define NCHUNK  (NN / BK)            // 128
#define KSTEPS  (BK / 16)            // 4

__global__ void __launch_bounds__(256) spmm_kernel(const float* __restrict__ adj,
                                                   float* __restrict__ out) {
    __shared__ __align__(16) char smem[2 * STAGEB];   // 36864 B
    const uint32_t sbase = static_cast<uint32_t>(__cvta_generic_to_shared(smem));

    const int t      = threadIdx.x;
    const int lane   = t & 31;
    const int wid    = t >> 5;
    const int warp_m = wid & 3;          // 4 m-warps, m16 each
    const int warp_n = wid >> 2;         // 2 n-warps, n16 each
    const int ctaM   = blockIdx.x * 64;

    // ---- A gmem addressing: thread covers rows m = (t>>4) + p*16 (p=0..3),
    //      cols (t&15)*4 .. +3 within the BK=64 chunk. Warp = 2 rows x 256 B.
    const size_t aoff0 = (size_t)(ctaM + (t >> 4)) * NN + (size_t)((t & 15) << 2);
    float4 av[4];

    auto ld_a = [&](int chunk) {
        const float* base = adj + aoff0 + chunk * BK;
#pragma unroll
        for (int p = 0; p < 4; ++p)
            av[p] = *reinterpret_cast<const float4*>(base + (size_t)p * 16 * NN);
    };

    auto st_a = [&](int stage) {
        const uint32_t ao = sbase + stage * STAGEB
                          + (uint32_t)(t >> 4) * PITCHB + (uint32_t)(t & 15) * 8;
#pragma unroll
        for (int p = 0; p < 4; ++p) {
            __nv_bfloat162 q0 = __floats2bfloat162_rn(av[p].x, av[p].y);
            __nv_bfloat162 q1 = __floats2bfloat162_rn(av[p].z, av[p].w);
            const uint32_t u0 = *reinterpret_cast<uint32_t*>(&q0);
            const uint32_t u1 = *reinterpret_cast<uint32_t*>(&q1);
            asm volatile("st.shared.v2.b32 [%0], {%1, %2};\n"
                         :: "r"(ao + p * (16 * PITCHB)), "r"(u0), "r"(u1));
        }
    };

    // ---- B cp.async: 64 rows (= dtype*32 + n) x 128 B per chunk = 8 KB;
    //      512 x 16B copies, 2 per thread.
    auto cp_b = [&](int chunk, int stage) {
        const uint32_t bo = sbase + stage * STAGEB + A_BYTES;
#pragma unroll
        for (int i = 0; i < 2; ++i) {
            const int idx = t + i * 256;
            const int row = idx >> 3;                  // 0..63 = dtype*32 + n
            const int seg = idx & 7;                   // 16B segment within row
            const __nv_bfloat16* src = g_B + (size_t)row * NN + chunk * BK + seg * 8;
            const uint32_t dst = bo + row * PITCHB + seg * 16;
            asm volatile("cp.async.cg.shared.global [%0], [%1], 16;\n"
                         :: "r"(dst), "l"(src));
        }
        asm volatile("cp.async.commit_group;\n" ::);
    };

    // ---- ldmatrix per-lane address offsets (stage/kstep-invariant parts).
    // A (m16k16 = 4 8x8s): lanes 0-15 -> rows m 0..15 @k0-7; 16-31 -> same rows @k8-15.
    const uint32_t aLdm = (uint32_t)(warp_m * 16 + (lane & 15)) * PITCHB
                        + (uint32_t)((lane >> 4) << 4);
    // B (two n8-tiles x k16 = 4 8x8s): rows are n; +16B selects k8-15.
    const uint32_t bRow = (uint32_t)(warp_n * 16 + ((lane >> 4) << 3) + (lane & 7));
    const uint32_t bK   = (uint32_t)(((lane >> 3) & 1) << 4);
    const uint32_t bHi  = bRow * PITCHB + bK;          // dtype 0 plane
    const uint32_t bLo  = (bRow + 32) * PITCHB + bK;   // dtype 1 plane

    float acc0[4] = {0.f, 0.f, 0.f, 0.f};   // n-tile 0
    float acc1[4] = {0.f, 0.f, 0.f, 0.f};   // n-tile 1

#define MMA_BF16(ACC, B0, B1)                                                   \
    asm volatile("mma.sync.aligned.m16n8k16.row.col.f32.bf16.bf16.f32 "         \
                 "{%0,%1,%2,%3}, {%4,%5,%6,%7}, {%8,%9}, {%0,%1,%2,%3};\n"      \
                 : "+f"(ACC[0]), "+f"(ACC[1]), "+f"(ACC[2]), "+f"(ACC[3])       \
                 : "r"(a0), "r"(a1), "r"(a2), "r"(a3), "r"(B0), "r"(B1))

    auto mma_chunk = [&](int stage) {
        const uint32_t sa = sbase + stage * STAGEB;
        const uint32_t sb = sa + A_BYTES;
#pragma unroll
        for (int ks = 0; ks < KSTEPS; ++ks) {
            uint32_t a0, a1, a2, a3, h0, h1, h2, h3, l0, l1, l2, l3;
            asm volatile("ldmatrix.sync.aligned.m8n8.x4.shared.b16 {%0,%1,%2,%3}, [%4];\n"
                         : "=r"(a0), "=r"(a1), "=r"(a2), "=r"(a3)
                         : "r"(sa + aLdm + ks * 32));
            asm volatile("ldmatrix.sync.aligned.m8n8.x4.shared.b16 {%0,%1,%2,%3}, [%4];\n"
                         : "=r"(h0), "=r"(h1), "=r"(h2), "=r"(h3)
                         : "r"(sb + bHi + ks * 32));
            asm volatile("ldmatrix.sync.aligned.m8n8.x4.shared.b16 {%0,%1,%2,%3}, [%4];\n"
                         : "=r"(l0), "=r"(l1), "=r"(l2), "=r"(l3)
                         : "r"(sb + bLo + ks * 32));
            MMA_BF16(acc0, h0, h1);   // n-tile 0, hi
            MMA_BF16(acc0, l0, l1);   // n-tile 0, lo
            MMA_BF16(acc1, h2, h3);   // n-tile 1, hi
            MMA_BF16(acc1, l2, l3);   // n-tile 1, lo
        }
    };

    // ---- 2-stage pipeline over 128 K-chunks.
    ld_a(0);
    cp_b(0, 0);
    for (int c = 0; c < NCHUNK; ++c) {
        const int cur = c & 1;
        st_a(cur);                               // A(c) regs -> smem[cur]
        if (c < NCHUNK - 1) {
            cp_b(c + 1, cur ^ 1);                // B(c+1) -> smem[nxt]
            ld_a(c + 1);                         // A(c+1) -> regs (after STS read them)
            asm volatile("cp.async.wait_group 1;\n" ::);   // B(c) arrived
        } else {
            asm volatile("cp.async.wait_group 0;\n" ::);
        }
        __syncthreads();                         // A STS + B visible to all warps
        mma_chunk(cur);
        __syncthreads();                         // guard next STS/cp.async overwrite
    }

    // ---- Epilogue: D fragment -> out (fp32, row-major, N=32), float2 stores.
    const int row0 = ctaM + warp_m * 16 + (lane >> 2);
    const int col0 = warp_n * 16 + (lane & 3) * 2;
    *reinterpret_cast<float2*>(out + (size_t)row0 * OUTF + col0) =
        make_float2(acc0[0], acc0[1]);
    *reinterpret_cast<float2*>(out + (size_t)(row0 + 8) * OUTF + col0) =
        make_float2(acc0[2], acc0[3]);
    *reinterpret_cast<float2*>(out + (size_t)row0 * OUTF + col0 + 8) =
        make_float2(acc1[0], acc1[1]);
    *reinterpret_cast<float2*>(out + (size_t)(row0 + 8) * OUTF + col0 + 8) =
        make_float2(acc1[2], acc1[3]);
}

// ---------------------------------------------------------------------------
// Launch: inputs per metadata order: h [8192*256] f32, adj [8192*8192] f32,
// W [256*32] f32; output f32 [8192*32].
// ---------------------------------------------------------------------------
extern "C" void kernel_launch(void* const* d_in, const int* in_sizes, int n_in,
                              void* d_out, int out_size) {
    (void)in_sizes; (void)n_in; (void)out_size;
    const float* h   = reinterpret_cast<const float*>(d_in[0]);
    const float* adj = reinterpret_cast<const float*>(d_in[1]);
    const float* W   = reinterpret_cast<const float*>(d_in[2]);
    float* out       = reinterpret_cast<float*>(d_out);

    hw_kernel<<<NN / 8, 256>>>(h, W);          // 1024 blocks: HW + hi/lo pack
    spmm_kernel<<<NN / 64, 256>>>(adj, out);   // 128 CTAs: adj @ HW via bf16 MMA
}

// round 6
// speedup vs baseline: 1.7766x; 1.7766x over previous
#include <cuda_runtime.h>
#include <cuda_bf16.h>
#include <cstdint>
#include <cstddef>

// Problem constants (fixed by the reference).
#define NN   8192   // N_NODES
#define INF  256    // IN_FEATURES
#define OUTF 32     // OUT_FEATURES

// ---------------------------------------------------------------------------
// Scratch: HW = h @ W split into bf16 hi/lo, stored transposed [plane][n][k],
// with a k-permutation applied WITHIN each 16-block so that the A operand can
// be fetched from gmem with single LDG.128 per lane per (kstep, row-half):
//   physical k (adj column order) -> packed position:
//     pos(k) = (k&2 ? 8 : 0) + ((k>>2)<<1) + (k&1)
// This makes smem position p hold HW[4*(p>>1)+(p&1)] for p<8 and
// HW[4*((p&7)>>1)+2+(p&1)] for p>=8, matching the float4 A fragment loads.
// ---------------------------------------------------------------------------
__device__ __nv_bfloat16 g_B[2 * OUTF * NN];

// ---------------------------------------------------------------------------
// Kernel 1: HW = h @ W (fp32) -> hi/lo bf16 planes in g_B (permuted k).
// Also zero-initializes out (grid*block == 8192*32 elements exactly).
// ---------------------------------------------------------------------------
__global__ void __launch_bounds__(256) hw_kernel(const float* __restrict__ h,
                                                 const float* __restrict__ W,
                                                 float* __restrict__ out) {
    __shared__ float Ws[INF * OUTF];            // 32 KB, [k][n]
    const int t = threadIdx.x;
    out[blockIdx.x * 256 + t] = 0.0f;           // zero-init for atomic epilogue
    for (int i = t; i < INF * OUTF; i += 256) Ws[i] = W[i];
    __syncthreads();

    const int c   = t & 31;                     // output feature n
    const int r   = t >> 5;
    const int row = blockIdx.x * 8 + r;         // node index = k of big GEMM

    const float4* hrow = reinterpret_cast<const float4*>(h + (size_t)row * INF);
    float acc = 0.f;
#pragma unroll 8
    for (int k4 = 0; k4 < INF / 4; ++k4) {
        const float4 hv = hrow[k4];
        const float* wp = &Ws[(k4 * 4) * OUTF + c];
        acc += hv.x * wp[0];
        acc += hv.y * wp[OUTF];
        acc += hv.z * wp[2 * OUTF];
        acc += hv.w * wp[3 * OUTF];
    }

    const __nv_bfloat16 hi = __float2bfloat16_rn(acc);
    const float rem        = acc - __bfloat162float(hi);
    const __nv_bfloat16 lo = __float2bfloat16_rn(rem);

    const int ph   = row & 15;
    const int p    = ((ph & 2) ? 8 : 0) | ((ph >> 2) << 1) | (ph & 1);
    const int kpos = (row & ~15) | p;
    g_B[(size_t)c * NN + kpos]          = hi;   // plane 0 (hi)
    g_B[(size_t)(OUTF + c) * NN + kpos] = lo;   // plane 1 (lo)
}

// ---------------------------------------------------------------------------
// Kernel 2: out += adj_chunk @ HW via bf16 mma.sync (hi+lo planes).
//
// Grid = 512 CTAs: 128 m-tiles (BM=64) x 4 K-splits (2048 K each).
// CTA = 128 threads = 4 warps; warp w owns rows [w*16, w*16+16) x all n=32.
//
// A: fragments loaded DIRECTLY from gmem: per lane per k16, two LDG.128
//    (rows r and r+8), fully coalesced (512B/instr), prefetch distance 1
//    chunk in registers, fp32 -> packed bf16 conversion in regs.
// B: 4-stage cp.async ring in smem (9216B/stage, pitch 144B -> conflict-free
//    ldmatrix), ONE __syncthreads per chunk; cp for stage reuse is issued
//    after the barrier so no second sync is needed.
// Epilogue: fp32 atomicAdd into zero-initialized out.
// ---------------------------------------------------------------------------
#define BK      64
#define STAGES  4
#define PITCH   144                    // bytes per B smem row (64 halfs + pad)
#define STAGEB  (64 * PITCH)           // 9216 B per stage (2 planes x 32 n)
#define KSPLIT  4
#define KPER    (NN / KSPLIT)          // 2048
#define CH      (KPER / BK)            // 32 chunks per CTA

#define MMA_BF16(ACC, A0, A1, A2, A3, B0, B1)                                   \
    asm volatile("mma.sync.aligned.m16n8k16.row.col.f32.bf16.bf16.f32 "         \
                 "{%0,%1,%2,%3}, {%4,%5,%6,%7}, {%8,%9}, {%0,%1,%2,%3};\n"      \
                 : "+f"((ACC)[0]), "+f"((ACC)[1]), "+f"((ACC)[2]), "+f"((ACC)[3])\
                 : "r"(A0), "r"(A1), "r"(A2), "r"(A3), "r"(B0), "r"(B1))

#define LDMX4(R0, R1, R2, R3, ADDR)                                             \
    asm volatile("ldmatrix.sync.aligned.m8n8.x4.shared.b16 {%0,%1,%2,%3}, [%4];\n"\
                 : "=r"(R0), "=r"(R1), "=r"(R2), "=r"(R3) : "r"(ADDR))

__global__ void __launch_bounds__(128) spmm_kernel(const float* __restrict__ adj,
                                                   float* __restrict__ out) {
    __shared__ __align__(16) char smem[STAGES * STAGEB];   // 36864 B
    const uint32_t sb0 = static_cast<uint32_t>(__cvta_generic_to_shared(smem));

    const int t    = threadIdx.x;
    const int lane = t & 31;
    const int wm   = t >> 5;                    // 4 m-warps
    const int mt   = blockIdx.x >> 2;           // m-tile 0..127
    const int ksid = blockIdx.x & 3;            // K-split id
    const int ctaM = mt * 64;
    const int kbase = ksid * KPER;

    // ---- A direct-fragment addressing: lane covers row r=lane/4 (and r+8),
    //      float4 at phys cols 4*(lane%4) within each k16 window.
    const int r  = lane >> 2;
    const int c4 = (lane & 3) << 2;
    const float* aptr = adj + (size_t)(ctaM + wm * 16 + r) * NN + kbase + c4;

    float4 pf[8];                               // prefetch: [kstep]{rows r, r+8}
    auto ld_a = [&](int chunk) {
        const float* p = aptr + chunk * BK;
#pragma unroll
        for (int ks = 0; ks < 4; ++ks) {
            pf[2 * ks]     = *reinterpret_cast<const float4*>(p + ks * 16);
            pf[2 * ks + 1] = *reinterpret_cast<const float4*>(p + ks * 16 + (size_t)8 * NN);
        }
    };

    // ---- B cp.async: 64 rows x 128B per chunk; 512 x 16B ops, 4/thread.
    auto cp_b = [&](int chunk) {
        if (chunk < CH) {
            const uint32_t bo = sb0 + (chunk & 3) * STAGEB;
            const __nv_bfloat16* s0 = g_B + kbase + chunk * BK;
#pragma unroll
            for (int i = 0; i < 4; ++i) {
                const int idx = t + i * 128;
                const int row = idx >> 3;       // 0..63 = plane*32 + n
                const int seg = idx & 7;
                const void* src = s0 + (size_t)row * NN + seg * 8;
                const uint32_t dst = bo + row * PITCH + seg * 16;
                asm volatile("cp.async.cg.shared.global [%0], [%1], 16;\n"
                             :: "r"(dst), "l"(src));
            }
        }
        asm volatile("cp.async.commit_group;\n" ::);
    };

    // ---- B ldmatrix lane offset within a 16-row group.
    const uint32_t brow = (uint32_t)(((lane >> 4) << 3) + (lane & 7));
    const uint32_t bko  = (uint32_t)(((lane >> 3) & 1) << 4);
    const uint32_t boff = brow * PITCH + bko;

    float acc[4][4] = {};                       // 4 n8-tiles
    uint32_t cur[16];                           // chunk's packed bf16 A frags

    ld_a(0);
    cp_b(0); cp_b(1); cp_b(2);

    for (int chunk = 0; chunk < CH; ++chunk) {
        // Convert prefetched A (frees pf for next chunk's loads).
#pragma unroll
        for (int ks = 0; ks < 4; ++ks) {
            const float4 f = pf[2 * ks], g = pf[2 * ks + 1];
            __nv_bfloat162 q0 = __floats2bfloat162_rn(f.x, f.y);   // a0
            __nv_bfloat162 q1 = __floats2bfloat162_rn(g.x, g.y);   // a1 (r+8)
            __nv_bfloat162 q2 = __floats2bfloat162_rn(f.z, f.w);   // a2
            __nv_bfloat162 q3 = __floats2bfloat162_rn(g.z, g.w);   // a3
            cur[4 * ks + 0] = *reinterpret_cast<uint32_t*>(&q0);
            cur[4 * ks + 1] = *reinterpret_cast<uint32_t*>(&q1);
            cur[4 * ks + 2] = *reinterpret_cast<uint32_t*>(&q2);
            cur[4 * ks + 3] = *reinterpret_cast<uint32_t*>(&q3);
        }
        if (chunk + 1 < CH) ld_a(chunk + 1);    // next chunk's A in flight

        asm volatile("cp.async.wait_group 2;\n" ::);   // B(chunk) arrived
        __syncthreads();                        // all warps done with chunk-1
        cp_b(chunk + 3);                        // safe: overwrites chunk-1's stage

        const uint32_t sb = sb0 + (chunk & 3) * STAGEB;
#pragma unroll
        for (int ks = 0; ks < 4; ++ks) {
            uint32_t h0,h1,h2,h3,h4,h5,h6,h7, l0,l1,l2,l3,l4,l5,l6,l7;
            const uint32_t ko = boff + ks * 32;
            LDMX4(h0,h1,h2,h3, sb + ko);                    // hi, n0-15
            LDMX4(h4,h5,h6,h7, sb + 16 * PITCH + ko);       // hi, n16-31
            LDMX4(l0,l1,l2,l3, sb + 32 * PITCH + ko);       // lo, n0-15
            LDMX4(l4,l5,l6,l7, sb + 48 * PITCH + ko);       // lo, n16-31
            const uint32_t a0 = cur[4*ks], a1 = cur[4*ks+1],
                           a2 = cur[4*ks+2], a3 = cur[4*ks+3];
            MMA_BF16(acc[0], a0,a1,a2,a3, h0,h1);
            MMA_BF16(acc[0], a0,a1,a2,a3, l0,l1);
            MMA_BF16(acc[1], a0,a1,a2,a3, h2,h3);
            MMA_BF16(acc[1], a0,a1,a2,a3, l2,l3);
            MMA_BF16(acc[2], a0,a1,a2,a3, h4,h5);
            MMA_BF16(acc[2], a0,a1,a2,a3, l4,l5);
            MMA_BF16(acc[3], a0,a1,a2,a3, h6,h7);
            MMA_BF16(acc[3], a0,a1,a2,a3, l6,l7);
        }
    }

    // ---- Epilogue: accumulate K-split partials with fp32 atomics.
    const int row0 = ctaM + wm * 16 + (lane >> 2);
    const int col0 = (lane & 3) * 2;
#pragma unroll
    for (int tile = 0; tile < 4; ++tile) {
        float* o0 = out + (size_t)row0 * OUTF + tile * 8 + col0;
        atomicAdd(o0,                acc[tile][0]);
        atomicAdd(o0 + 1,            acc[tile][1]);
        atomicAdd(o0 + 8 * OUTF,     acc[tile][2]);
        atomicAdd(o0 + 8 * OUTF + 1, acc[tile][3]);
    }
}

// ---------------------------------------------------------------------------
// Launch: inputs: h [8192*256] f32, adj [8192*8192] f32, W [256*32] f32;
// output f32 [8192*32].
// ---------------------------------------------------------------------------
extern "C" void kernel_launch(void* const* d_in, const int* in_sizes, int n_in,
                              void* d_out, int out_size) {
    (void)in_sizes; (void)n_in; (void)out_size;
    const float* h   = reinterpret_cast<const float*>(d_in[0]);
    const float* adj = reinterpret_cast<const float*>(d_in[1]);
    const float* W   = reinterpret_cast<const float*>(d_in[2]);
    float* out       = reinterpret_cast<float*>(d_out);

    hw_kernel<<<NN / 8, 256>>>(h, W, out);                 // HW pack + out=0
    spmm_kernel<<<(NN / 64) * KSPLIT, 128>>>(adj, out);    // 512 CTAs
}